// round 3
// baseline (speedup 1.0000x reference)
#include <cuda_runtime.h>

#define TT   512
#define BSZ  256
#define DIN  64
#define HH   128
#define G4   (4*HH)      // 512 gate rows per layer
#define K0   (DIN+HH)    // 192
#define K1   (2*HH)      // 256
#define NB0  (K0/4)      // 48 k-blocks layer0
#define NB1  (K1/4)      // 64 k-blocks layer1
#define BPC  4           // batch elements per CTA
#define NCTA (BSZ/BPC)   // 64
#define NTHR 512

// Blocked transposed weights: element (kb, g, i) = W[g][4*kb+i] of the
// concatenated [W_ih | W_hh] row-major matrix. One float4 per (kb,g):
// thread owning row g loads 4 consecutive k in a single coalesced LDG.128.
__device__ float4 g_W0B[NB0 * G4];
__device__ float4 g_W1B[NB1 * G4];

__global__ void prep_kernel(const float* __restrict__ Wih0,
                            const float* __restrict__ Whh0,
                            const float* __restrict__ Wih1,
                            const float* __restrict__ Whh1)
{
    int idx = blockIdx.x * blockDim.x + threadIdx.x;
    int stride = gridDim.x * blockDim.x;
    float* p0 = (float*)g_W0B;
    float* p1 = (float*)g_W1B;
    for (int e = idx; e < K0 * G4; e += stride) {
        int k = e / G4, g = e % G4;
        float v = (k < DIN) ? Wih0[g * DIN + k] : Whh0[g * HH + (k - DIN)];
        p0[((k >> 2) * G4 + g) * 4 + (k & 3)] = v;
    }
    for (int e = idx; e < K1 * G4; e += stride) {
        int k = e / G4, g = e % G4;
        float v = (k < HH) ? Wih1[g * HH + k] : Whh1[g * HH + (k - HH)];
        p1[((k >> 2) * G4 + g) * 4 + (k & 3)] = v;
    }
}

__device__ __forceinline__ void fma2(unsigned long long& d,
                                     unsigned long long a,
                                     unsigned long long b)
{
    asm("fma.rn.f32x2 %0, %1, %2, %0;" : "+l"(d) : "l"(a), "l"(b));
}
__device__ __forceinline__ float flo(unsigned long long v) {
    return __uint_as_float((unsigned)(v & 0xffffffffu));
}
__device__ __forceinline__ float fhi(unsigned long long v) {
    return __uint_as_float((unsigned)(v >> 32));
}
__device__ __forceinline__ float sigf(float x) {
    return 1.0f / (1.0f + __expf(-x));
}

__global__ void __launch_bounds__(NTHR, 1)
lstm_kernel(const float* __restrict__ state,
            const float* __restrict__ b_ih0, const float* __restrict__ b_hh0,
            const float* __restrict__ b_ih1, const float* __restrict__ b_hh1,
            const float* __restrict__ W_out, const float* __restrict__ b_out,
            float* __restrict__ out)
{
    // Double-buffered concatenated activation vectors (x|h0), (h0|h1)
    __shared__ __align__(16) float sxh0[2][BPC][K0];
    __shared__ __align__(16) float sxh1[2][BPC][K1];
    __shared__ float swout[HH];
    __shared__ float sred[16];
    __shared__ float sbout;

    const int tid  = threadIdx.x;
    const int b    = tid >> 7;        // batch element 0..3 (local)
    const int j    = tid & (HH - 1);  // hidden unit 0..127
    const int warp = tid >> 5;
    const int b0   = blockIdx.x * BPC;

    if (tid < HH) swout[tid] = W_out[tid];
    if (tid == 0) sbout = b_out[0];

    // zero h parts of both buffers
    sxh0[0][b][DIN + j] = 0.0f;  sxh0[1][b][DIN + j] = 0.0f;
    sxh1[0][b][j]       = 0.0f;  sxh1[1][b][j]       = 0.0f;
    sxh1[0][b][HH + j]  = 0.0f;  sxh1[1][b][HH + j]  = 0.0f;

    // per-thread gate biases (i, f, g, o rows: j, 128+j, 256+j, 384+j)
    const float bi0 = b_ih0[j]          + b_hh0[j];
    const float bf0 = b_ih0[HH + j]     + b_hh0[HH + j];
    const float bg0 = b_ih0[2 * HH + j] + b_hh0[2 * HH + j];
    const float bo0 = b_ih0[3 * HH + j] + b_hh0[3 * HH + j];
    const float bi1 = b_ih1[j]          + b_hh1[j];
    const float bf1 = b_ih1[HH + j]     + b_hh1[HH + j];
    const float bg1 = b_ih1[2 * HH + j] + b_hh1[2 * HH + j];
    const float bo1 = b_ih1[3 * HH + j] + b_hh1[3 * HH + j];

    float c0 = 0.0f, c1 = 0.0f;       // cell states live in registers

    const unsigned long long* w0base = ((const unsigned long long*)g_W0B) + 2 * j;
    const unsigned long long* w1base = ((const unsigned long long*)g_W1B) + 2 * j;

    __syncthreads();

    for (int t = 0; t < TT; ++t) {
        const int p = t & 1;

        // ---- x_t into current buffer ----
        if (tid < BPC * DIN) {
            int lb = tid >> 6, k = tid & (DIN - 1);
            sxh0[p][lb][k] = state[(t * BSZ + b0 + lb) * DIN + k];
        }
        __syncthreads();  // S1: x(t) + h0(t-1) ready in sxh0[p]

        // ---- layer 0: 4 gate dots (len 192) for unit j, batch b ----
        float h0;
        {
            unsigned long long ai = 0, af = 0, ag = 0, ao = 0;
            const unsigned long long* xv = (const unsigned long long*)sxh0[p][b];
            #pragma unroll 4
            for (int kb = 0; kb < NB0; ++kb) {
                unsigned long long x0 = xv[2 * kb];
                unsigned long long x1 = xv[2 * kb + 1];
                const unsigned long long* wk = w0base + (size_t)kb * (2 * G4);
                unsigned long long wi0 = wk[0],          wi1 = wk[1];
                unsigned long long wf0 = wk[2 * HH],     wf1 = wk[2 * HH + 1];
                unsigned long long wg0 = wk[4 * HH],     wg1 = wk[4 * HH + 1];
                unsigned long long wo0 = wk[6 * HH],     wo1 = wk[6 * HH + 1];
                fma2(ai, wi0, x0); fma2(ai, wi1, x1);
                fma2(af, wf0, x0); fma2(af, wf1, x1);
                fma2(ag, wg0, x0); fma2(ag, wg1, x1);
                fma2(ao, wo0, x0); fma2(ao, wo1, x1);
            }
            float gi = sigf (flo(ai) + fhi(ai) + bi0);
            float gf = sigf (flo(af) + fhi(af) + bf0);
            float gg = tanhf(flo(ag) + fhi(ag) + bg0);
            float go = sigf (flo(ao) + fhi(ao) + bo0);
            c0 = gf * c0 + gi * gg;
            h0 = go * tanhf(c0);
        }
        // publish h0: to layer1's current buffer and next step's layer0 buffer
        sxh1[p][b][j]            = h0;
        sxh0[p ^ 1][b][DIN + j]  = h0;
        __syncthreads();  // S2: h0(t) ready in sxh1[p]

        // ---- layer 1: 4 gate dots (len 256) for unit j, batch b ----
        float h1;
        {
            unsigned long long ai = 0, af = 0, ag = 0, ao = 0;
            const unsigned long long* xv = (const unsigned long long*)sxh1[p][b];
            #pragma unroll 4
            for (int kb = 0; kb < NB1; ++kb) {
                unsigned long long x0 = xv[2 * kb];
                unsigned long long x1 = xv[2 * kb + 1];
                const unsigned long long* wk = w1base + (size_t)kb * (2 * G4);
                unsigned long long wi0 = wk[0],          wi1 = wk[1];
                unsigned long long wf0 = wk[2 * HH],     wf1 = wk[2 * HH + 1];
                unsigned long long wg0 = wk[4 * HH],     wg1 = wk[4 * HH + 1];
                unsigned long long wo0 = wk[6 * HH],     wo1 = wk[6 * HH + 1];
                fma2(ai, wi0, x0); fma2(ai, wi1, x1);
                fma2(af, wf0, x0); fma2(af, wf1, x1);
                fma2(ag, wg0, x0); fma2(ag, wg1, x1);
                fma2(ao, wo0, x0); fma2(ao, wo1, x1);
            }
            float gi = sigf (flo(ai) + fhi(ai) + bi1);
            float gf = sigf (flo(af) + fhi(af) + bf1);
            float gg = tanhf(flo(ag) + fhi(ag) + bg1);
            float go = sigf (flo(ao) + fhi(ao) + bo1);
            c1 = gf * c1 + gi * gg;
            h1 = go * tanhf(c1);
        }
        // publish h1 for next step's layer1 buffer
        sxh1[p ^ 1][b][HH + j] = h1;

        // ---- head: dot(h1, W_out) per batch (4 warps per batch elem) ----
        float pr = h1 * swout[j];
        #pragma unroll
        for (int off = 16; off; off >>= 1)
            pr += __shfl_down_sync(0xffffffffu, pr, off);
        if ((tid & 31) == 0) sred[warp] = pr;
        __syncthreads();  // S3: sred + h1 visible

        if (tid < BPC) {
            out[t * BSZ + b0 + tid] = sred[4 * tid] + sred[4 * tid + 1]
                                    + sred[4 * tid + 2] + sred[4 * tid + 3] + sbout;
        }
    }
}

extern "C" void kernel_launch(void* const* d_in, const int* in_sizes, int n_in,
                              void* d_out, int out_size)
{
    const float* state = (const float*)d_in[0];
    const float* W_ih0 = (const float*)d_in[1];
    const float* W_hh0 = (const float*)d_in[2];
    const float* b_ih0 = (const float*)d_in[3];
    const float* b_hh0 = (const float*)d_in[4];
    const float* W_ih1 = (const float*)d_in[5];
    const float* W_hh1 = (const float*)d_in[6];
    const float* b_ih1 = (const float*)d_in[7];
    const float* b_hh1 = (const float*)d_in[8];
    const float* W_out = (const float*)d_in[9];
    const float* b_out = (const float*)d_in[10];
    float* out = (float*)d_out;

    prep_kernel<<<224, 512>>>(W_ih0, W_hh0, W_ih1, W_hh1);
    lstm_kernel<<<NCTA, NTHR>>>(state, b_ih0, b_hh0, b_ih1, b_hh1,
                                W_out, b_out, out);
}

// round 4
// speedup vs baseline: 1.4546x; 1.4546x over previous
#include <cuda_runtime.h>

#define TT   512
#define BSZ  256
#define DIN  64
#define HH   128
#define G4   (4*HH)      // 512 gate rows per layer
#define K0   (DIN+HH)    // 192
#define K1   (2*HH)      // 256
#define NB0  (K0/4)      // 48 k-blocks layer0
#define NB1  (K1/4)      // 64 k-blocks layer1
#define BPC  4           // batch elements per CTA
#define NCTA (BSZ/BPC)   // 64
#define NTHR 512

// Blocked transposed weights: g_WxB[kb*G4 + g] = float4 of W[g][4kb .. 4kb+3]
// (concatenated [W_ih | W_hh] row). Warp lanes = consecutive g -> each
// LDG.128 is a fully coalesced 512B warp transaction.
__device__ float4 g_W0B[NB0 * G4];
__device__ float4 g_W1B[NB1 * G4];

__global__ void prep_kernel(const float* __restrict__ Wih0,
                            const float* __restrict__ Whh0,
                            const float* __restrict__ Wih1,
                            const float* __restrict__ Whh1)
{
    int idx = blockIdx.x * blockDim.x + threadIdx.x;
    int stride = gridDim.x * blockDim.x;
    float* p0 = (float*)g_W0B;
    float* p1 = (float*)g_W1B;
    for (int e = idx; e < K0 * G4; e += stride) {
        int k = e / G4, g = e % G4;
        float v = (k < DIN) ? Wih0[g * DIN + k] : Whh0[g * HH + (k - DIN)];
        p0[((k >> 2) * G4 + g) * 4 + (k & 3)] = v;
    }
    for (int e = idx; e < K1 * G4; e += stride) {
        int k = e / G4, g = e % G4;
        float v = (k < HH) ? Wih1[g * HH + k] : Whh1[g * HH + (k - HH)];
        p1[((k >> 2) * G4 + g) * 4 + (k & 3)] = v;
    }
}

__device__ __forceinline__ void fma2(unsigned long long& d,
                                     unsigned long long a,
                                     unsigned long long b)
{
    asm("fma.rn.f32x2 %0, %1, %2, %0;" : "+l"(d) : "l"(a), "l"(b));
}
__device__ __forceinline__ float flo(unsigned long long v) {
    return __uint_as_float((unsigned)(v & 0xffffffffu));
}
__device__ __forceinline__ float fhi(unsigned long long v) {
    return __uint_as_float((unsigned)(v >> 32));
}
__device__ __forceinline__ float sigf(float x) {
    return 1.0f / (1.0f + __expf(-x));
}

__global__ void __launch_bounds__(NTHR, 1)
lstm_kernel(const float* __restrict__ state,
            const float* __restrict__ b_ih0, const float* __restrict__ b_hh0,
            const float* __restrict__ b_ih1, const float* __restrict__ b_hh1,
            const float* __restrict__ W_out, const float* __restrict__ b_out,
            float* __restrict__ out)
{
    __shared__ __align__(16) float sxh0[BPC][K0];   // [x_t | h0_prev]
    __shared__ __align__(16) float sxh1[BPC][K1];   // [h0_new | h1_prev]
    __shared__ float sc0[BPC][HH];
    __shared__ float sc1[BPC][HH];
    __shared__ float sg[BPC][G4];                    // gate pre-activations
    __shared__ float swout[HH];
    __shared__ float sred[16];
    __shared__ float sbout;

    const int tid = threadIdx.x;
    const int b0  = blockIdx.x * BPC;
    const int g   = tid;                 // gate row owned by this thread

    if (tid < HH) swout[tid] = W_out[tid];
    if (tid == 0) sbout = b_out[0];
    for (int i = tid; i < BPC * HH; i += NTHR) {
        int bb = i / HH, j = i % HH;
        sc0[bb][j] = 0.0f;
        sc1[bb][j] = 0.0f;
        sxh0[bb][DIN + j] = 0.0f;
        sxh1[bb][j]       = 0.0f;
        sxh1[bb][HH + j]  = 0.0f;
    }
    const float bias0 = b_ih0[g] + b_hh0[g];
    const float bias1 = b_ih1[g] + b_hh1[g];
    __syncthreads();

    const int bb = tid >> 7;             // activation-phase mapping
    const int j  = tid & (HH - 1);

    const unsigned long long* w0 = (const unsigned long long*)g_W0B + 2 * g;
    const unsigned long long* w1 = (const unsigned long long*)g_W1B + 2 * g;

    for (int t = 0; t < TT; ++t) {
        // ---- A: load x_t for our 4 batch elements ----
        if (tid < BPC * DIN) {
            int lb = tid >> 6, k = tid & (DIN - 1);
            sxh0[lb][k] = state[(t * BSZ + b0 + lb) * DIN + k];
        }
        __syncthreads();  // S1

        // ---- B: layer0 gates, row g, 4 batch, f32x2 ----
        {
            unsigned long long a0 = 0, a1 = 0, a2 = 0, a3 = 0;
            const ulonglong2* x0 = (const ulonglong2*)sxh0[0];
            const ulonglong2* x1 = (const ulonglong2*)sxh0[1];
            const ulonglong2* x2 = (const ulonglong2*)sxh0[2];
            const ulonglong2* x3 = (const ulonglong2*)sxh0[3];
            #pragma unroll 4
            for (int kb = 0; kb < NB0; ++kb) {
                const ulonglong2 w = *(const ulonglong2*)(w0 + (size_t)kb * (2 * G4));
                ulonglong2 v0 = x0[kb], v1 = x1[kb], v2 = x2[kb], v3 = x3[kb];
                fma2(a0, w.x, v0.x); fma2(a0, w.y, v0.y);
                fma2(a1, w.x, v1.x); fma2(a1, w.y, v1.y);
                fma2(a2, w.x, v2.x); fma2(a2, w.y, v2.y);
                fma2(a3, w.x, v3.x); fma2(a3, w.y, v3.y);
            }
            sg[0][g] = flo(a0) + fhi(a0) + bias0;
            sg[1][g] = flo(a1) + fhi(a1) + bias0;
            sg[2][g] = flo(a2) + fhi(a2) + bias0;
            sg[3][g] = flo(a3) + fhi(a3) + bias0;
        }
        __syncthreads();  // S2

        // ---- C: layer0 activations ----
        {
            float gi = sigf (sg[bb][j]);
            float gf = sigf (sg[bb][HH + j]);
            float gg = tanhf(sg[bb][2 * HH + j]);
            float go = sigf (sg[bb][3 * HH + j]);
            float c  = gf * sc0[bb][j] + gi * gg;
            sc0[bb][j] = c;
            float h = go * tanhf(c);
            sxh0[bb][DIN + j] = h;
            sxh1[bb][j]       = h;
        }
        __syncthreads();  // S3

        // ---- D: layer1 gates, row g, 4 batch, f32x2 ----
        {
            unsigned long long a0 = 0, a1 = 0, a2 = 0, a3 = 0;
            const ulonglong2* x0 = (const ulonglong2*)sxh1[0];
            const ulonglong2* x1 = (const ulonglong2*)sxh1[1];
            const ulonglong2* x2 = (const ulonglong2*)sxh1[2];
            const ulonglong2* x3 = (const ulonglong2*)sxh1[3];
            #pragma unroll 4
            for (int kb = 0; kb < NB1; ++kb) {
                const ulonglong2 w = *(const ulonglong2*)(w1 + (size_t)kb * (2 * G4));
                ulonglong2 v0 = x0[kb], v1 = x1[kb], v2 = x2[kb], v3 = x3[kb];
                fma2(a0, w.x, v0.x); fma2(a0, w.y, v0.y);
                fma2(a1, w.x, v1.x); fma2(a1, w.y, v1.y);
                fma2(a2, w.x, v2.x); fma2(a2, w.y, v2.y);
                fma2(a3, w.x, v3.x); fma2(a3, w.y, v3.y);
            }
            sg[0][g] = flo(a0) + fhi(a0) + bias1;
            sg[1][g] = flo(a1) + fhi(a1) + bias1;
            sg[2][g] = flo(a2) + fhi(a2) + bias1;
            sg[3][g] = flo(a3) + fhi(a3) + bias1;
        }
        __syncthreads();  // S4

        // ---- E: layer1 activations + head partial dot ----
        {
            float gi = sigf (sg[bb][j]);
            float gf = sigf (sg[bb][HH + j]);
            float gg = tanhf(sg[bb][2 * HH + j]);
            float go = sigf (sg[bb][3 * HH + j]);
            float c  = gf * sc1[bb][j] + gi * gg;
            sc1[bb][j] = c;
            float h = go * tanhf(c);
            sxh1[bb][HH + j] = h;
            float p = h * swout[j];
            #pragma unroll
            for (int off = 16; off; off >>= 1)
                p += __shfl_down_sync(0xffffffffu, p, off);
            if ((tid & 31) == 0) sred[tid >> 5] = p;
        }
        __syncthreads();  // S5

        // ---- F: finalize head output ----
        if (tid < BPC) {
            out[t * BSZ + b0 + tid] = sred[4 * tid] + sred[4 * tid + 1]
                                    + sred[4 * tid + 2] + sred[4 * tid + 3] + sbout;
        }
        // sred not rewritten until after S4 of next iteration -> safe
    }
}

extern "C" void kernel_launch(void* const* d_in, const int* in_sizes, int n_in,
                              void* d_out, int out_size)
{
    const float* state = (const float*)d_in[0];
    const float* W_ih0 = (const float*)d_in[1];
    const float* W_hh0 = (const float*)d_in[2];
    const float* b_ih0 = (const float*)d_in[3];
    const float* b_hh0 = (const float*)d_in[4];
    const float* W_ih1 = (const float*)d_in[5];
    const float* W_hh1 = (const float*)d_in[6];
    const float* b_ih1 = (const float*)d_in[7];
    const float* b_hh1 = (const float*)d_in[8];
    const float* W_out = (const float*)d_in[9];
    const float* b_out = (const float*)d_in[10];
    float* out = (float*)d_out;

    prep_kernel<<<224, 512>>>(W_ih0, W_hh0, W_ih1, W_hh1);
    lstm_kernel<<<NCTA, NTHR>>>(state, b_ih0, b_hh0, b_ih1, b_hh1,
                                W_out, b_out, out);
}

// round 5
// speedup vs baseline: 1.5337x; 1.0544x over previous
#include <cuda_runtime.h>

#define TT   512
#define BSZ  256
#define DIN  64
#define HH   128
#define G4   (4*HH)      // 512 gate rows per layer
#define K0   (DIN+HH)    // 192
#define K1   (2*HH)      // 256
#define NB0  (K0/4)      // 48
#define NB1  (K1/4)      // 64
#define BPC  4
#define NCTA (BSZ/BPC)   // 64
#define NTHR 512

// Blocked transposed weights: g_WxB[kb*G4 + g] = float4 of W[g][4kb..4kb+3]
__device__ float4 g_W0B[NB0 * G4];
__device__ float4 g_W1B[NB1 * G4];

__global__ void prep_kernel(const float* __restrict__ Wih0,
                            const float* __restrict__ Whh0,
                            const float* __restrict__ Wih1,
                            const float* __restrict__ Whh1)
{
    int idx = blockIdx.x * blockDim.x + threadIdx.x;
    int stride = gridDim.x * blockDim.x;
    float* p0 = (float*)g_W0B;
    float* p1 = (float*)g_W1B;
    for (int e = idx; e < K0 * G4; e += stride) {
        int k = e / G4, g = e % G4;
        float v = (k < DIN) ? Wih0[g * DIN + k] : Whh0[g * HH + (k - DIN)];
        p0[((k >> 2) * G4 + g) * 4 + (k & 3)] = v;
    }
    for (int e = idx; e < K1 * G4; e += stride) {
        int k = e / G4, g = e % G4;
        float v = (k < HH) ? Wih1[g * HH + k] : Whh1[g * HH + (k - HH)];
        p1[((k >> 2) * G4 + g) * 4 + (k & 3)] = v;
    }
}

__device__ __forceinline__ void fma2(unsigned long long& d,
                                     unsigned long long a,
                                     unsigned long long b)
{
    asm("fma.rn.f32x2 %0, %1, %2, %0;" : "+l"(d) : "l"(a), "l"(b));
}
__device__ __forceinline__ float flo(unsigned long long v) {
    return __uint_as_float((unsigned)(v & 0xffffffffu));
}
__device__ __forceinline__ float fhi(unsigned long long v) {
    return __uint_as_float((unsigned)(v >> 32));
}
// MUFU-only activations (saturation-safe at +-inf)
__device__ __forceinline__ float sigf(float x) {
    return __fdividef(1.0f, 1.0f + __expf(-x));
}
__device__ __forceinline__ float tanhfast(float x) {
    return 1.0f - __fdividef(2.0f, __expf(2.0f * x) + 1.0f);
}

__global__ void __launch_bounds__(NTHR, 1)
lstm_kernel(const float* __restrict__ state,
            const float* __restrict__ b_ih0, const float* __restrict__ b_hh0,
            const float* __restrict__ b_ih1, const float* __restrict__ b_hh1,
            const float* __restrict__ W_out, const float* __restrict__ b_out,
            float* __restrict__ out)
{
    __shared__ __align__(16) float sxh0[2][BPC][K0];   // [x(t) | h0(t-1)]
    __shared__ __align__(16) float sxh1[2][BPC][K1];   // [h0(t) | h1(t-1)]
    __shared__ float sg0[BPC][G4];                     // L0(t) pre-acts
    __shared__ float sg1[BPC][G4];                     // L1(t-1) pre-acts
    __shared__ float swout[HH];
    __shared__ float sred[16];
    __shared__ float sbout;

    const int tid = threadIdx.x;
    const int b0  = blockIdx.x * BPC;
    const int g   = tid;

    if (tid < HH) swout[tid] = W_out[tid];
    if (tid == 0) sbout = b_out[0];
    // zero recurrent parts of both parities
    {
        int bb = tid >> 7, j = tid & (HH - 1);
        sxh0[0][bb][DIN + j] = 0.0f;  sxh0[1][bb][DIN + j] = 0.0f;
        sxh1[0][bb][j]       = 0.0f;  sxh1[1][bb][j]       = 0.0f;
        sxh1[0][bb][HH + j]  = 0.0f;  sxh1[1][bb][HH + j]  = 0.0f;
    }
    // x(0)
    if (tid < 64) {
        int lb = tid >> 4, k4 = tid & 15;
        ((float4*)sxh0[0][lb])[k4] =
            ((const float4*)(state + (0 * BSZ + b0 + lb) * DIN))[k4];
    }
    const float bias0 = b_ih0[g] + b_hh0[g];
    const float bias1 = b_ih1[g] + b_hh1[g];
    float c0 = 0.0f, c1 = 0.0f;
    const int bb = tid >> 7;
    const int j  = tid & (HH - 1);

    const ulonglong2* w0p = (const ulonglong2*)g_W0B + g;
    const ulonglong2* w1p = (const ulonglong2*)g_W1B + g;

    __syncthreads();

    for (int t = 0; t < TT; ++t) {
        const int p = t & 1;

        // out(t-2) from sred written in act(t-1)
        if (t >= 2 && tid < BPC) {
            out[(t - 2) * BSZ + b0 + tid] = sred[4 * tid] + sred[4 * tid + 1]
                                          + sred[4 * tid + 2] + sred[4 * tid + 3] + sbout;
        }
        // prefetch x(t+1) into other parity
        if (tid < 64 && t + 1 < TT) {
            int lb = tid >> 4, k4 = tid & 15;
            ((float4*)sxh0[p ^ 1][lb])[k4] =
                ((const float4*)(state + ((t + 1) * BSZ + b0 + lb) * DIN))[k4];
        }

        // ---- fused dot superphase: L0(t) + L1(t-1), 8 accumulators ----
        {
            unsigned long long a00 = 0, a01 = 0, a02 = 0, a03 = 0;  // L0(t)
            unsigned long long a10 = 0, a11 = 0, a12 = 0, a13 = 0;  // L1(t-1)
            const ulonglong2* x00 = (const ulonglong2*)sxh0[p][0];
            const ulonglong2* x01 = (const ulonglong2*)sxh0[p][1];
            const ulonglong2* x02 = (const ulonglong2*)sxh0[p][2];
            const ulonglong2* x03 = (const ulonglong2*)sxh0[p][3];
            const ulonglong2* x10 = (const ulonglong2*)sxh1[p ^ 1][0];
            const ulonglong2* x11 = (const ulonglong2*)sxh1[p ^ 1][1];
            const ulonglong2* x12 = (const ulonglong2*)sxh1[p ^ 1][2];
            const ulonglong2* x13 = (const ulonglong2*)sxh1[p ^ 1][3];
            #pragma unroll 2
            for (int kb = 0; kb < NB0; ++kb) {
                ulonglong2 wa = w0p[(size_t)kb * G4];
                ulonglong2 wb = w1p[(size_t)kb * G4];
                ulonglong2 v0 = x00[kb], v1 = x01[kb], v2 = x02[kb], v3 = x03[kb];
                ulonglong2 u0 = x10[kb], u1 = x11[kb], u2 = x12[kb], u3 = x13[kb];
                fma2(a00, wa.x, v0.x); fma2(a00, wa.y, v0.y);
                fma2(a01, wa.x, v1.x); fma2(a01, wa.y, v1.y);
                fma2(a02, wa.x, v2.x); fma2(a02, wa.y, v2.y);
                fma2(a03, wa.x, v3.x); fma2(a03, wa.y, v3.y);
                fma2(a10, wb.x, u0.x); fma2(a10, wb.y, u0.y);
                fma2(a11, wb.x, u1.x); fma2(a11, wb.y, u1.y);
                fma2(a12, wb.x, u2.x); fma2(a12, wb.y, u2.y);
                fma2(a13, wb.x, u3.x); fma2(a13, wb.y, u3.y);
            }
            #pragma unroll 4
            for (int kb = NB0; kb < NB1; ++kb) {
                ulonglong2 wb = w1p[(size_t)kb * G4];
                ulonglong2 u0 = x10[kb], u1 = x11[kb], u2 = x12[kb], u3 = x13[kb];
                fma2(a10, wb.x, u0.x); fma2(a10, wb.y, u0.y);
                fma2(a11, wb.x, u1.x); fma2(a11, wb.y, u1.y);
                fma2(a12, wb.x, u2.x); fma2(a12, wb.y, u2.y);
                fma2(a13, wb.x, u3.x); fma2(a13, wb.y, u3.y);
            }
            sg0[0][g] = flo(a00) + fhi(a00) + bias0;
            sg0[1][g] = flo(a01) + fhi(a01) + bias0;
            sg0[2][g] = flo(a02) + fhi(a02) + bias0;
            sg0[3][g] = flo(a03) + fhi(a03) + bias0;
            sg1[0][g] = flo(a10) + fhi(a10) + bias1;
            sg1[1][g] = flo(a11) + fhi(a11) + bias1;
            sg1[2][g] = flo(a12) + fhi(a12) + bias1;
            sg1[3][g] = flo(a13) + fhi(a13) + bias1;
        }
        __syncthreads();  // B1

        // ---- act(t): L0(t) and (t>=1) L1(t-1) ----
        {
            float gi = sigf    (sg0[bb][j]);
            float gf = sigf    (sg0[bb][HH + j]);
            float gg = tanhfast(sg0[bb][2 * HH + j]);
            float go = sigf    (sg0[bb][3 * HH + j]);
            c0 = gf * c0 + gi * gg;
            float h0 = go * tanhfast(c0);
            sxh0[p ^ 1][bb][DIN + j] = h0;   // for L0(t+1)
            sxh1[p][bb][j]           = h0;   // for L1(t)
        }
        if (t >= 1) {
            float gi = sigf    (sg1[bb][j]);
            float gf = sigf    (sg1[bb][HH + j]);
            float gg = tanhfast(sg1[bb][2 * HH + j]);
            float go = sigf    (sg1[bb][3 * HH + j]);
            c1 = gf * c1 + gi * gg;
            float h1 = go * tanhfast(c1);
            sxh1[p][bb][HH + j] = h1;        // h1(t-1) for L1(t)
            float pr = h1 * swout[j];
            #pragma unroll
            for (int off = 16; off; off >>= 1)
                pr += __shfl_down_sync(0xffffffffu, pr, off);
            if ((tid & 31) == 0) sred[tid >> 5] = pr;
        }
        __syncthreads();  // B2
    }

    // ---- epilogue: L1(511) ----
    if (tid < BPC) {
        out[(TT - 2) * BSZ + b0 + tid] = sred[4 * tid] + sred[4 * tid + 1]
                                       + sred[4 * tid + 2] + sred[4 * tid + 3] + sbout;
    }
    {
        unsigned long long a10 = 0, a11 = 0, a12 = 0, a13 = 0;
        const ulonglong2* x10 = (const ulonglong2*)sxh1[1][0];  // t=512 -> p^1 = 1
        const ulonglong2* x11 = (const ulonglong2*)sxh1[1][1];
        const ulonglong2* x12 = (const ulonglong2*)sxh1[1][2];
        const ulonglong2* x13 = (const ulonglong2*)sxh1[1][3];
        #pragma unroll 4
        for (int kb = 0; kb < NB1; ++kb) {
            ulonglong2 wb = w1p[(size_t)kb * G4];
            ulonglong2 u0 = x10[kb], u1 = x11[kb], u2 = x12[kb], u3 = x13[kb];
            fma2(a10, wb.x, u0.x); fma2(a10, wb.y, u0.y);
            fma2(a11, wb.x, u1.x); fma2(a11, wb.y, u1.y);
            fma2(a12, wb.x, u2.x); fma2(a12, wb.y, u2.y);
            fma2(a13, wb.x, u3.x); fma2(a13, wb.y, u3.y);
        }
        sg1[0][g] = flo(a10) + fhi(a10) + bias1;
        sg1[1][g] = flo(a11) + fhi(a11) + bias1;
        sg1[2][g] = flo(a12) + fhi(a12) + bias1;
        sg1[3][g] = flo(a13) + fhi(a13) + bias1;
    }
    __syncthreads();
    {
        float gi = sigf    (sg1[bb][j]);
        float gf = sigf    (sg1[bb][HH + j]);
        float gg = tanhfast(sg1[bb][2 * HH + j]);
        float go = sigf    (sg1[bb][3 * HH + j]);
        c1 = gf * c1 + gi * gg;
        float h1 = go * tanhfast(c1);
        float pr = h1 * swout[j];
        #pragma unroll
        for (int off = 16; off; off >>= 1)
            pr += __shfl_down_sync(0xffffffffu, pr, off);
        if ((tid & 31) == 0) sred[tid >> 5] = pr;
    }
    __syncthreads();
    if (tid < BPC) {
        out[(TT - 1) * BSZ + b0 + tid] = sred[4 * tid] + sred[4 * tid + 1]
                                       + sred[4 * tid + 2] + sred[4 * tid + 3] + sbout;
    }
}

extern "C" void kernel_launch(void* const* d_in, const int* in_sizes, int n_in,
                              void* d_out, int out_size)
{
    const float* state = (const float*)d_in[0];
    const float* W_ih0 = (const float*)d_in[1];
    const float* W_hh0 = (const float*)d_in[2];
    const float* b_ih0 = (const float*)d_in[3];
    const float* b_hh0 = (const float*)d_in[4];
    const float* W_ih1 = (const float*)d_in[5];
    const float* W_hh1 = (const float*)d_in[6];
    const float* b_ih1 = (const float*)d_in[7];
    const float* b_hh1 = (const float*)d_in[8];
    const float* W_out = (const float*)d_in[9];
    const float* b_out = (const float*)d_in[10];
    float* out = (float*)d_out;

    prep_kernel<<<224, 512>>>(W_ih0, W_hh0, W_ih1, W_hh1);
    lstm_kernel<<<NCTA, NTHR>>>(state, b_ih0, b_hh0, b_ih1, b_hh1,
                                W_out, b_out, out);
}

// round 6
// speedup vs baseline: 2.3862x; 1.5558x over previous
#include <cuda_runtime.h>

#define TT   512
#define BSZ  256
#define DIN  64
#define HH   128
#define G4   (4*HH)      // 512 gate rows per layer
#define K0   (DIN+HH)    // 192
#define K1   (2*HH)      // 256
#define NB0  (K0/4)      // 48
#define NB1  (K1/4)      // 64
#define BPC  4
#define NGRP (BSZ/BPC)   // 64 batch groups
#define NCTA (2*NGRP)    // 128 CTAs: even = layer0, odd = layer1
#define NTHR 512
#define RING 8

// Blocked transposed weights: g_WxB[kb*G4 + g] = float4 of W[g][4kb..4kb+3]
__device__ float4 g_W0B[NB0 * G4];
__device__ float4 g_W1B[NB1 * G4];

// h0 handoff ring: [slot][group][bb*128+j], plus monotonic flow counters
__device__ __align__(16) float g_h0buf[RING][NGRP][NTHR];
__device__ unsigned g_fcnt[NGRP];   // producer: steps published
__device__ unsigned g_bcnt[NGRP];   // consumer: steps consumed

__global__ void prep_kernel(const float* __restrict__ Wih0,
                            const float* __restrict__ Whh0,
                            const float* __restrict__ Wih1,
                            const float* __restrict__ Whh1)
{
    int idx = blockIdx.x * blockDim.x + threadIdx.x;
    int stride = gridDim.x * blockDim.x;
    if (blockIdx.x == 0 && threadIdx.x < NGRP) {
        g_fcnt[threadIdx.x] = 0;
        g_bcnt[threadIdx.x] = 0;
    }
    float* p0 = (float*)g_W0B;
    float* p1 = (float*)g_W1B;
    for (int e = idx; e < K0 * G4; e += stride) {
        int k = e / G4, g = e % G4;
        float v = (k < DIN) ? Wih0[g * DIN + k] : Whh0[g * HH + (k - DIN)];
        p0[((k >> 2) * G4 + g) * 4 + (k & 3)] = v;
    }
    for (int e = idx; e < K1 * G4; e += stride) {
        int k = e / G4, g = e % G4;
        float v = (k < HH) ? Wih1[g * HH + k] : Whh1[g * HH + (k - HH)];
        p1[((k >> 2) * G4 + g) * 4 + (k & 3)] = v;
    }
}

__device__ __forceinline__ void fma2(unsigned long long& d,
                                     unsigned long long a,
                                     unsigned long long b)
{
    asm("fma.rn.f32x2 %0, %1, %2, %0;" : "+l"(d) : "l"(a), "l"(b));
}
__device__ __forceinline__ float flo(unsigned long long v) {
    return __uint_as_float((unsigned)(v & 0xffffffffu));
}
__device__ __forceinline__ float fhi(unsigned long long v) {
    return __uint_as_float((unsigned)(v >> 32));
}
__device__ __forceinline__ float sigf(float x) {
    return __fdividef(1.0f, 1.0f + __expf(-x));
}
__device__ __forceinline__ float tanhfast(float x) {
    return 1.0f - __fdividef(2.0f, __expf(2.0f * x) + 1.0f);
}
__device__ __forceinline__ unsigned ld_acq(const unsigned* p) {
    unsigned v;
    asm volatile("ld.acquire.gpu.global.u32 %0, [%1];" : "=r"(v) : "l"(p));
    return v;
}
__device__ __forceinline__ void st_rel(unsigned* p, unsigned v) {
    asm volatile("st.release.gpu.global.u32 [%0], %1;" :: "l"(p), "r"(v));
}

__global__ void __launch_bounds__(NTHR, 1)
lstm_kernel(const float* __restrict__ state,
            const float* __restrict__ b_ih0, const float* __restrict__ b_hh0,
            const float* __restrict__ b_ih1, const float* __restrict__ b_hh1,
            const float* __restrict__ W_out, const float* __restrict__ b_out,
            float* __restrict__ out)
{
    __shared__ __align__(16) float sxh0[2][BPC][K0];   // A: [x(t) | h0(t-1)]
    __shared__ __align__(16) float sxh1[2][BPC][K1];   // B: [h0(t) | h1(t-1)]
    __shared__ float sg[BPC][G4];
    __shared__ float swout[HH];
    __shared__ float sred[16];
    __shared__ float sbout;

    const int grp  = blockIdx.x >> 1;
    const int role = blockIdx.x & 1;
    const int b0   = grp * BPC;
    const int tid  = threadIdx.x;
    const int g    = tid;
    const int bb   = tid >> 7;
    const int j    = tid & (HH - 1);

    if (role == 0) {
        // ================= CTA-A: layer 0 producer =================
        const float bias0 = b_ih0[g] + b_hh0[g];
        sxh0[0][bb][DIN + j] = 0.0f;
        sxh0[1][bb][DIN + j] = 0.0f;
        if (tid < 64) {   // x(0)
            int lb = tid >> 4, k4 = tid & 15;
            ((float4*)sxh0[0][lb])[k4] =
                ((const float4*)(state + (b0 + lb) * DIN))[k4];
        }
        float c0 = 0.0f;
        const ulonglong2* w0p = (const ulonglong2*)g_W0B + g;
        __syncthreads();

        for (int t = 0; t < TT; ++t) {
            const int p = t & 1;
            // prefetch x(t+1)
            if (tid < 64 && t + 1 < TT) {
                int lb = tid >> 4, k4 = tid & 15;
                ((float4*)sxh0[p ^ 1][lb])[k4] =
                    ((const float4*)(state + ((t + 1) * BSZ + b0 + lb) * DIN))[k4];
            }
            // ring backpressure: B must have consumed slot's previous tenant
            if (tid == 0 && t >= RING) {
                while ((int)ld_acq(&g_bcnt[grp]) < t - RING + 1) { }
            }
            // dot L0(t): gate row g, 4 batches
            {
                unsigned long long a0 = 0, a1 = 0, a2 = 0, a3 = 0;
                const ulonglong2* x0 = (const ulonglong2*)sxh0[p][0];
                const ulonglong2* x1 = (const ulonglong2*)sxh0[p][1];
                const ulonglong2* x2 = (const ulonglong2*)sxh0[p][2];
                const ulonglong2* x3 = (const ulonglong2*)sxh0[p][3];
                #pragma unroll 4
                for (int kb = 0; kb < NB0; ++kb) {
                    ulonglong2 w = w0p[(size_t)kb * G4];
                    ulonglong2 v0 = x0[kb], v1 = x1[kb], v2 = x2[kb], v3 = x3[kb];
                    fma2(a0, w.x, v0.x); fma2(a0, w.y, v0.y);
                    fma2(a1, w.x, v1.x); fma2(a1, w.y, v1.y);
                    fma2(a2, w.x, v2.x); fma2(a2, w.y, v2.y);
                    fma2(a3, w.x, v3.x); fma2(a3, w.y, v3.y);
                }
                sg[0][g] = flo(a0) + fhi(a0) + bias0;
                sg[1][g] = flo(a1) + fhi(a1) + bias0;
                sg[2][g] = flo(a2) + fhi(a2) + bias0;
                sg[3][g] = flo(a3) + fhi(a3) + bias0;
            }
            __syncthreads();  // S2: gates ready, backpressure cleared
            // act -> h0(t)
            {
                float gi = sigf    (sg[bb][j]);
                float gf = sigf    (sg[bb][HH + j]);
                float gg = tanhfast(sg[bb][2 * HH + j]);
                float go = sigf    (sg[bb][3 * HH + j]);
                c0 = gf * c0 + gi * gg;
                float h0 = go * tanhfast(c0);
                sxh0[p ^ 1][bb][DIN + j] = h0;            // recurrence
                g_h0buf[t & (RING - 1)][grp][tid] = h0;   // handoff
            }
            __threadfence();
            __syncthreads();  // S3
            if (tid == 0) st_rel(&g_fcnt[grp], (unsigned)(t + 1));
        }
    } else {
        // ================= CTA-B: layer 1 + head consumer =================
        const float bias1 = b_ih1[g] + b_hh1[g];
        if (tid < HH) swout[tid] = W_out[tid];
        if (tid == 0) sbout = b_out[0];
        sxh1[0][bb][HH + j] = 0.0f;
        sxh1[1][bb][HH + j] = 0.0f;
        float c1 = 0.0f;
        const ulonglong2* w1p = (const ulonglong2*)g_W1B + g;
        __syncthreads();

        for (int t = 0; t < TT; ++t) {
            const int q = t & 1;
            if (tid == 0) {
                while ((int)ld_acq(&g_fcnt[grp]) < t + 1) { }
            }
            __syncthreads();  // T1: h0(t) published
            if (tid < 128) {  // copy h0(t) -> smem (float4, coalesced)
                ((float4*)sxh1[q][tid >> 5])[tid & 31] =
                    ((const float4*)g_h0buf[t & (RING - 1)][grp])[tid];
            }
            __syncthreads();  // T2: copy done
            if (tid == 0) st_rel(&g_bcnt[grp], (unsigned)(t + 1));
            // dot L1(t): gate row g, 4 batches
            {
                unsigned long long a0 = 0, a1 = 0, a2 = 0, a3 = 0;
                const ulonglong2* x0 = (const ulonglong2*)sxh1[q][0];
                const ulonglong2* x1 = (const ulonglong2*)sxh1[q][1];
                const ulonglong2* x2 = (const ulonglong2*)sxh1[q][2];
                const ulonglong2* x3 = (const ulonglong2*)sxh1[q][3];
                #pragma unroll 4
                for (int kb = 0; kb < NB1; ++kb) {
                    ulonglong2 w = w1p[(size_t)kb * G4];
                    ulonglong2 v0 = x0[kb], v1 = x1[kb], v2 = x2[kb], v3 = x3[kb];
                    fma2(a0, w.x, v0.x); fma2(a0, w.y, v0.y);
                    fma2(a1, w.x, v1.x); fma2(a1, w.y, v1.y);
                    fma2(a2, w.x, v2.x); fma2(a2, w.y, v2.y);
                    fma2(a3, w.x, v3.x); fma2(a3, w.y, v3.y);
                }
                sg[0][g] = flo(a0) + fhi(a0) + bias1;
                sg[1][g] = flo(a1) + fhi(a1) + bias1;
                sg[2][g] = flo(a2) + fhi(a2) + bias1;
                sg[3][g] = flo(a3) + fhi(a3) + bias1;
            }
            __syncthreads();  // T3
            // act -> h1(t), head partial
            {
                float gi = sigf    (sg[bb][j]);
                float gf = sigf    (sg[bb][HH + j]);
                float gg = tanhfast(sg[bb][2 * HH + j]);
                float go = sigf    (sg[bb][3 * HH + j]);
                c1 = gf * c1 + gi * gg;
                float h1 = go * tanhfast(c1);
                sxh1[q ^ 1][bb][HH + j] = h1;   // recurrence
                float pr = h1 * swout[j];
                #pragma unroll
                for (int off = 16; off; off >>= 1)
                    pr += __shfl_down_sync(0xffffffffu, pr, off);
                if ((tid & 31) == 0) sred[tid >> 5] = pr;
            }
            __syncthreads();  // T4
            if (tid < BPC) {
                out[t * BSZ + b0 + tid] = sred[4 * tid] + sred[4 * tid + 1]
                                        + sred[4 * tid + 2] + sred[4 * tid + 3] + sbout;
            }
        }
    }
}

extern "C" void kernel_launch(void* const* d_in, const int* in_sizes, int n_in,
                              void* d_out, int out_size)
{
    const float* state = (const float*)d_in[0];
    const float* W_ih0 = (const float*)d_in[1];
    const float* W_hh0 = (const float*)d_in[2];
    const float* b_ih0 = (const float*)d_in[3];
    const float* b_hh0 = (const float*)d_in[4];
    const float* W_ih1 = (const float*)d_in[5];
    const float* W_hh1 = (const float*)d_in[6];
    const float* b_ih1 = (const float*)d_in[7];
    const float* b_hh1 = (const float*)d_in[8];
    const float* W_out = (const float*)d_in[9];
    const float* b_out = (const float*)d_in[10];
    float* out = (float*)d_out;

    prep_kernel<<<224, 512>>>(W_ih0, W_hh0, W_ih1, W_hh1);
    lstm_kernel<<<NCTA, NTHR>>>(state, b_ih0, b_hh0, b_ih1, b_hh1,
                                W_out, b_out, out);
}